// round 1
// baseline (speedup 1.0000x reference)
#include <cuda_runtime.h>
#include <cuda_bf16.h>

#define P   2048
#define E   768
#define H   64
#define NQ  12

// ---------------- scratch (no allocations allowed) ----------------
__device__ float g_q[NQ * P * H];   // [q][p][h]  6 MB
__device__ float g_k[P * H];        // [s][h]
__device__ float g_v[P * H];        // [s][h]
__device__ float g_m[P * NQ * H];   // merged attn [p][q*64+h]  6 MB

// ============================================================================
// K1: fused QKV projection.  C[p, n] = sum_e x[p,e] * Wcat[n][e] + bias[n]
//     n in [0,768)   -> q head n>>6, dim n&63
//     n in [768,832) -> k
//     n in [832,896) -> v
// 64x64 tile, BK=16, 256 threads, 4x4 microtile.
// ============================================================================
__global__ __launch_bounds__(256) void proj_kernel(
    const float* __restrict__ x,
    const float* __restrict__ Wq, const float* __restrict__ bq,
    const float* __restrict__ Wk, const float* __restrict__ bk,
    const float* __restrict__ Wv, const float* __restrict__ bv)
{
    __shared__ float As[16][64];
    __shared__ float Bs[16][64];

    const int t  = threadIdx.x;
    const int tx = t & 15;
    const int ty = t >> 4;
    const int row0 = blockIdx.x * 64;
    const int n0   = blockIdx.y * 64;

    // whole 64-wide tile lives in one weight segment (segments 64-aligned)
    const float* Wbase;
    const float* bias;
    if (n0 < 768)      { Wbase = Wq + (size_t)n0 * E;         bias = bq + n0; }
    else if (n0 < 832) { Wbase = Wk + (size_t)(n0 - 768) * E; bias = bk + (n0 - 768); }
    else               { Wbase = Wv + (size_t)(n0 - 832) * E; bias = bv + (n0 - 832); }

    const int lr = t >> 2;         // 0..63 (tile row / tile col)
    const int lk = (t & 3) * 4;    // 0,4,8,12

    float acc[4][4] = {};

    for (int k0 = 0; k0 < E; k0 += 16) {
        float4 av = *(const float4*)&x[(size_t)(row0 + lr) * E + k0 + lk];
        float4 bv4 = *(const float4*)&Wbase[(size_t)lr * E + k0 + lk];
        As[lk + 0][lr] = av.x;  As[lk + 1][lr] = av.y;
        As[lk + 2][lr] = av.z;  As[lk + 3][lr] = av.w;
        Bs[lk + 0][lr] = bv4.x; Bs[lk + 1][lr] = bv4.y;
        Bs[lk + 2][lr] = bv4.z; Bs[lk + 3][lr] = bv4.w;
        __syncthreads();
        #pragma unroll
        for (int kk = 0; kk < 16; kk++) {
            float4 a = *(const float4*)&As[kk][ty * 4];
            float4 b = *(const float4*)&Bs[kk][tx * 4];
            float ar[4] = {a.x, a.y, a.z, a.w};
            float br[4] = {b.x, b.y, b.z, b.w};
            #pragma unroll
            for (int i = 0; i < 4; i++)
                #pragma unroll
                for (int j = 0; j < 4; j++)
                    acc[i][j] += ar[i] * br[j];
        }
        __syncthreads();
    }

    #pragma unroll
    for (int i = 0; i < 4; i++) {
        int row = row0 + ty * 4 + i;
        #pragma unroll
        for (int j = 0; j < 4; j++) {
            int n = n0 + tx * 4 + j;
            float v = acc[i][j] + bias[tx * 4 + j];
            if (n < 768) {
                int qi = n >> 6, h = n & 63;
                g_q[((size_t)qi * P + row) * H + h] = v;
            } else if (n < 832) {
                g_k[(size_t)row * H + (n - 768)] = v;
            } else {
                g_v[(size_t)row * H + (n - 832)] = v;
            }
        }
    }
}

// ============================================================================
// K2: scores[head][p][s] = (q[head][p][:] . k[s][:]) * 0.125, written straight
// into the probs region of d_out. 64x64 tile, K = 64 (BK=16).
// ============================================================================
__global__ __launch_bounds__(256) void scores_kernel(float* __restrict__ probs)
{
    __shared__ float As[16][64];
    __shared__ float Bs[16][64];

    const int t  = threadIdx.x;
    const int tx = t & 15;
    const int ty = t >> 4;
    const int row0 = blockIdx.x * 64;
    const int col0 = blockIdx.y * 64;
    const int head = blockIdx.z;

    const float* A = g_q + (size_t)head * P * H;   // [p][h]
    const int lr = t >> 2;
    const int lk = (t & 3) * 4;

    float acc[4][4] = {};

    #pragma unroll
    for (int k0 = 0; k0 < H; k0 += 16) {
        float4 av = *(const float4*)&A[(size_t)(row0 + lr) * H + k0 + lk];
        float4 bv = *(const float4*)&g_k[(size_t)(col0 + lr) * H + k0 + lk];
        As[lk + 0][lr] = av.x; As[lk + 1][lr] = av.y;
        As[lk + 2][lr] = av.z; As[lk + 3][lr] = av.w;
        Bs[lk + 0][lr] = bv.x; Bs[lk + 1][lr] = bv.y;
        Bs[lk + 2][lr] = bv.z; Bs[lk + 3][lr] = bv.w;
        __syncthreads();
        #pragma unroll
        for (int kk = 0; kk < 16; kk++) {
            float4 a = *(const float4*)&As[kk][ty * 4];
            float4 b = *(const float4*)&Bs[kk][tx * 4];
            float ar[4] = {a.x, a.y, a.z, a.w};
            float br[4] = {b.x, b.y, b.z, b.w};
            #pragma unroll
            for (int i = 0; i < 4; i++)
                #pragma unroll
                for (int j = 0; j < 4; j++)
                    acc[i][j] += ar[i] * br[j];
        }
        __syncthreads();
    }

    const size_t hbase = (size_t)head * P * P;
    #pragma unroll
    for (int i = 0; i < 4; i++) {
        size_t rbase = hbase + (size_t)(row0 + ty * 4 + i) * P + col0;
        #pragma unroll
        for (int j = 0; j < 4; j++)
            probs[rbase + tx * 4 + j] = acc[i][j] * 0.125f;
    }
}

// ============================================================================
// K3: in-place row softmax over 2048 columns. One CTA per (head,row),
// 256 threads x 8 elements each.
// ============================================================================
__global__ __launch_bounds__(256) void softmax_kernel(float* __restrict__ probs)
{
    __shared__ float red[8];
    float* rowp = probs + (size_t)blockIdx.x * P;
    const int t = threadIdx.x;
    const int lane = t & 31;
    const int w = t >> 5;

    float4 v0 = ((float4*)rowp)[t];
    float4 v1 = ((float4*)rowp)[t + 256];

    // --- max ---
    float m = fmaxf(fmaxf(fmaxf(v0.x, v0.y), fmaxf(v0.z, v0.w)),
                    fmaxf(fmaxf(v1.x, v1.y), fmaxf(v1.z, v1.w)));
    #pragma unroll
    for (int o = 16; o; o >>= 1) m = fmaxf(m, __shfl_xor_sync(0xFFFFFFFFu, m, o));
    if (lane == 0) red[w] = m;
    __syncthreads();
    float bm = red[0];
    #pragma unroll
    for (int i = 1; i < 8; i++) bm = fmaxf(bm, red[i]);
    __syncthreads();

    // --- exp & sum ---
    v0.x = __expf(v0.x - bm); v0.y = __expf(v0.y - bm);
    v0.z = __expf(v0.z - bm); v0.w = __expf(v0.w - bm);
    v1.x = __expf(v1.x - bm); v1.y = __expf(v1.y - bm);
    v1.z = __expf(v1.z - bm); v1.w = __expf(v1.w - bm);
    float s = (v0.x + v0.y + v0.z + v0.w) + (v1.x + v1.y + v1.z + v1.w);
    #pragma unroll
    for (int o = 16; o; o >>= 1) s += __shfl_xor_sync(0xFFFFFFFFu, s, o);
    if (lane == 0) red[w] = s;
    __syncthreads();
    float bs = 0.f;
    #pragma unroll
    for (int i = 0; i < 8; i++) bs += red[i];

    float inv = 1.0f / bs;
    v0.x *= inv; v0.y *= inv; v0.z *= inv; v0.w *= inv;
    v1.x *= inv; v1.y *= inv; v1.z *= inv; v1.w *= inv;
    ((float4*)rowp)[t]       = v0;
    ((float4*)rowp)[t + 256] = v1;
}

// ============================================================================
// K4: attn[head][p][h] = sum_s probs[head][p][s] * v[s][h]
// -> written directly into merged layout g_m[p][head*64+h].
// 64 rows x 64 cols (full N), BK=32 over s.
// ============================================================================
__global__ __launch_bounds__(256) void pv_kernel(const float* __restrict__ probs)
{
    __shared__ float As[32][64];   // [kk][row]
    __shared__ float Bs[32][64];   // [kk][h]

    const int t  = threadIdx.x;
    const int tx = t & 15;
    const int ty = t >> 4;
    const int row0 = blockIdx.x * 64;
    const int head = blockIdx.z;

    const float* A = probs + (size_t)head * P * P;   // [p][s]
    float acc[4][4] = {};

    for (int k0 = 0; k0 < P; k0 += 32) {
        #pragma unroll
        for (int l = 0; l < 2; l++) {
            int idx = t + l * 256;            // 0..511 float4 slots
            // A tile: 64 rows x 32 k
            int r  = idx >> 3;
            int kq = (idx & 7) * 4;
            float4 av = *(const float4*)&A[(size_t)(row0 + r) * P + k0 + kq];
            As[kq + 0][r] = av.x; As[kq + 1][r] = av.y;
            As[kq + 2][r] = av.z; As[kq + 3][r] = av.w;
            // B tile: 32 s x 64 h
            int s  = idx >> 4;
            int h4 = (idx & 15) * 4;
            float4 bv = *(const float4*)&g_v[(size_t)(k0 + s) * H + h4];
            *(float4*)&Bs[s][h4] = bv;
        }
        __syncthreads();
        #pragma unroll
        for (int kk = 0; kk < 32; kk++) {
            float4 a = *(const float4*)&As[kk][ty * 4];
            float4 b = *(const float4*)&Bs[kk][tx * 4];
            float ar[4] = {a.x, a.y, a.z, a.w};
            float br[4] = {b.x, b.y, b.z, b.w};
            #pragma unroll
            for (int i = 0; i < 4; i++)
                #pragma unroll
                for (int j = 0; j < 4; j++)
                    acc[i][j] += ar[i] * br[j];
        }
        __syncthreads();
    }

    #pragma unroll
    for (int i = 0; i < 4; i++) {
        size_t rbase = (size_t)(row0 + ty * 4 + i) * (NQ * H) + head * H;
        #pragma unroll
        for (int j = 0; j < 4; j++)
            g_m[rbase + tx * 4 + j] = acc[i][j];
    }
}

// ============================================================================
// K5: out[p][h] = sum_j g_m[p][j] * Wo[h][j] + bo[h]   (M=2048, N=64, K=768)
// ============================================================================
__global__ __launch_bounds__(256) void outproj_kernel(
    const float* __restrict__ Wo, const float* __restrict__ bo,
    float* __restrict__ out)
{
    __shared__ float As[16][64];
    __shared__ float Bs[16][64];

    const int t  = threadIdx.x;
    const int tx = t & 15;
    const int ty = t >> 4;
    const int row0 = blockIdx.x * 64;

    const int lr = t >> 2;
    const int lk = (t & 3) * 4;

    float acc[4][4] = {};

    for (int k0 = 0; k0 < NQ * H; k0 += 16) {
        float4 av = *(const float4*)&g_m[(size_t)(row0 + lr) * (NQ * H) + k0 + lk];
        float4 bv = *(const float4*)&Wo[(size_t)lr * (NQ * H) + k0 + lk];
        As[lk + 0][lr] = av.x; As[lk + 1][lr] = av.y;
        As[lk + 2][lr] = av.z; As[lk + 3][lr] = av.w;
        Bs[lk + 0][lr] = bv.x; Bs[lk + 1][lr] = bv.y;
        Bs[lk + 2][lr] = bv.z; Bs[lk + 3][lr] = bv.w;
        __syncthreads();
        #pragma unroll
        for (int kk = 0; kk < 16; kk++) {
            float4 a = *(const float4*)&As[kk][ty * 4];
            float4 b = *(const float4*)&Bs[kk][tx * 4];
            float ar[4] = {a.x, a.y, a.z, a.w};
            float br[4] = {b.x, b.y, b.z, b.w};
            #pragma unroll
            for (int i = 0; i < 4; i++)
                #pragma unroll
                for (int j = 0; j < 4; j++)
                    acc[i][j] += ar[i] * br[j];
        }
        __syncthreads();
    }

    #pragma unroll
    for (int i = 0; i < 4; i++) {
        int row = row0 + ty * 4 + i;
        #pragma unroll
        for (int j = 0; j < 4; j++) {
            int h = tx * 4 + j;
            out[(size_t)row * H + h] = acc[i][j] + bo[h];
        }
    }
}

// ============================================================================
// launch
// ============================================================================
extern "C" void kernel_launch(void* const* d_in, const int* in_sizes, int n_in,
                              void* d_out, int out_size)
{
    const float* x  = (const float*)d_in[0];
    const float* Wq = (const float*)d_in[1];
    const float* bq = (const float*)d_in[2];
    const float* Wk = (const float*)d_in[3];
    const float* bk = (const float*)d_in[4];
    const float* Wv = (const float*)d_in[5];
    const float* bv = (const float*)d_in[6];
    const float* Wo = (const float*)d_in[7];
    const float* bo = (const float*)d_in[8];

    float* out   = (float*)d_out;            // [1, 2048, 64]
    float* probs = out + (size_t)P * H;      // [12, 2048, 2048]

    proj_kernel<<<dim3(P / 64, (E + 2 * H) / 64), 256>>>(x, Wq, bq, Wk, bk, Wv, bv);
    scores_kernel<<<dim3(P / 64, P / 64, NQ), 256>>>(probs);
    softmax_kernel<<<NQ * P, 256>>>(probs);
    pv_kernel<<<dim3(P / 64, 1, NQ), 256>>>(probs);
    outproj_kernel<<<P / 64, 256>>>(Wo, bo, out);
}

// round 2
// speedup vs baseline: 1.7068x; 1.7068x over previous
#include <cuda_runtime.h>
#include <cuda_bf16.h>
#include <cstdint>

#define P   2048
#define E   768
#define H   64
#define NQ  12

// ---------------- scratch (no allocations allowed) ----------------
__device__ float g_q[NQ * P * H];   // [q][p][h]  6 MB
__device__ float g_k[P * H];        // [s][h]
__device__ float g_v[P * H];        // [s][h]
__device__ float g_m[P * NQ * H];   // merged attn [p][q*64+h]  6 MB

// ---------------- tf32 helpers ----------------
__device__ __forceinline__ uint32_t f2tf(float x) {
    uint32_t r;
    asm("cvt.rna.tf32.f32 %0, %1;" : "=r"(r) : "f"(x));
    return r;
}

__device__ __forceinline__ void mma8(float* c, const uint32_t* a, const uint32_t* b) {
    asm volatile(
        "mma.sync.aligned.m16n8k8.row.col.f32.tf32.tf32.f32 "
        "{%0,%1,%2,%3}, {%4,%5,%6,%7}, {%8,%9}, {%0,%1,%2,%3};"
        : "+f"(c[0]), "+f"(c[1]), "+f"(c[2]), "+f"(c[3])
        : "r"(a[0]), "r"(a[1]), "r"(a[2]), "r"(a[3]),
          "r"(b[0]), "r"(b[1]));
}

// ============================================================================
// K1: fused QKV projection (scalar fp32, unchanged from round 1).
// ============================================================================
__global__ __launch_bounds__(256) void proj_kernel(
    const float* __restrict__ x,
    const float* __restrict__ Wq, const float* __restrict__ bq,
    const float* __restrict__ Wk, const float* __restrict__ bk,
    const float* __restrict__ Wv, const float* __restrict__ bv)
{
    __shared__ float As[16][64];
    __shared__ float Bs[16][64];

    const int t  = threadIdx.x;
    const int tx = t & 15;
    const int ty = t >> 4;
    const int row0 = blockIdx.x * 64;
    const int n0   = blockIdx.y * 64;

    const float* Wbase;
    const float* bias;
    if (n0 < 768)      { Wbase = Wq + (size_t)n0 * E;         bias = bq + n0; }
    else if (n0 < 832) { Wbase = Wk + (size_t)(n0 - 768) * E; bias = bk + (n0 - 768); }
    else               { Wbase = Wv + (size_t)(n0 - 832) * E; bias = bv + (n0 - 832); }

    const int lr = t >> 2;
    const int lk = (t & 3) * 4;

    float acc[4][4] = {};

    for (int k0 = 0; k0 < E; k0 += 16) {
        float4 av = *(const float4*)&x[(size_t)(row0 + lr) * E + k0 + lk];
        float4 bv4 = *(const float4*)&Wbase[(size_t)lr * E + k0 + lk];
        As[lk + 0][lr] = av.x;  As[lk + 1][lr] = av.y;
        As[lk + 2][lr] = av.z;  As[lk + 3][lr] = av.w;
        Bs[lk + 0][lr] = bv4.x; Bs[lk + 1][lr] = bv4.y;
        Bs[lk + 2][lr] = bv4.z; Bs[lk + 3][lr] = bv4.w;
        __syncthreads();
        #pragma unroll
        for (int kk = 0; kk < 16; kk++) {
            float4 a = *(const float4*)&As[kk][ty * 4];
            float4 b = *(const float4*)&Bs[kk][tx * 4];
            float ar[4] = {a.x, a.y, a.z, a.w};
            float br[4] = {b.x, b.y, b.z, b.w};
            #pragma unroll
            for (int i = 0; i < 4; i++)
                #pragma unroll
                for (int j = 0; j < 4; j++)
                    acc[i][j] += ar[i] * br[j];
        }
        __syncthreads();
    }

    #pragma unroll
    for (int i = 0; i < 4; i++) {
        int row = row0 + ty * 4 + i;
        #pragma unroll
        for (int j = 0; j < 4; j++) {
            int n = n0 + tx * 4 + j;
            float v = acc[i][j] + bias[tx * 4 + j];
            if (n < 768) {
                int qi = n >> 6, h = n & 63;
                g_q[((size_t)qi * P + row) * H + h] = v;
            } else if (n < 832) {
                g_k[(size_t)row * H + (n - 768)] = v;
            } else {
                g_v[(size_t)row * H + (n - 832)] = v;
            }
        }
    }
}

// ============================================================================
// K2: scores via tf32 mma.sync.  C[head][p][s] = (q . k) * 0.125
// CTA: 128 rows x 128 cols, 8 warps, warp tile 64x32 (m-tiles 4, n-tiles 4).
// K = 64 split into 2 chunks of 32.
// As[r][k]  pad 36 (stride%32==4 -> A-frag banks 4g+tg, conflict-free)
// Bs[h][s]  pad 136 (stride%32==8 -> B-frag banks 8tg+g, conflict-free)
// ============================================================================
__global__ __launch_bounds__(256) void scores_mma_kernel(float* __restrict__ probs)
{
    __shared__ uint32_t As[128][36];
    __shared__ uint32_t Bs[32][136];

    const int t    = threadIdx.x;
    const int lane = t & 31;
    const int wid  = t >> 5;
    const int wm   = wid >> 2;        // 0..1  (64-row group)
    const int wn   = wid & 3;         // 0..3  (32-col group)
    const int g    = lane >> 2;
    const int tg   = lane & 3;
    const int head = blockIdx.z;
    const int row0 = blockIdx.x * 128;
    const int col0 = blockIdx.y * 128;

    const float* q = g_q + (size_t)head * P * H;

    float acc[4][4][4] = {};

    #pragma unroll
    for (int kb = 0; kb < 2; kb++) {
        const int h0c = kb * 32;
        // A: 128 rows x 32 k  (coalesced float4, contiguous smem rows)
        #pragma unroll
        for (int it = 0; it < 4; it++) {
            int idx = t + it * 256;              // 0..1023
            int r = idx >> 3, c4 = (idx & 7) * 4;
            float4 v = *(const float4*)&q[(size_t)(row0 + r) * H + h0c + c4];
            uint4 u = { f2tf(v.x), f2tf(v.y), f2tf(v.z), f2tf(v.w) };
            *(uint4*)&As[r][c4] = u;
        }
        // B: transpose 128 s x 32 h  ->  Bs[h][s]. Warp wid owns h rows wid*4..+4.
        {
            const int hw = wid * 4;
            #pragma unroll
            for (int si = 0; si < 4; si++) {
                int s = si * 32 + lane;
                float4 v = *(const float4*)&g_k[(size_t)(col0 + s) * H + h0c + hw];
                Bs[hw + 0][s] = f2tf(v.x);
                Bs[hw + 1][s] = f2tf(v.y);
                Bs[hw + 2][s] = f2tf(v.z);
                Bs[hw + 3][s] = f2tf(v.w);
            }
        }
        __syncthreads();

        #pragma unroll
        for (int kc = 0; kc < 4; kc++) {
            uint32_t a[4][4], b[4][2];
            #pragma unroll
            for (int mi = 0; mi < 4; mi++) {
                int rb = wm * 64 + mi * 16;
                a[mi][0] = As[rb + g    ][kc * 8 + tg    ];
                a[mi][1] = As[rb + g + 8][kc * 8 + tg    ];
                a[mi][2] = As[rb + g    ][kc * 8 + tg + 4];
                a[mi][3] = As[rb + g + 8][kc * 8 + tg + 4];
            }
            #pragma unroll
            for (int ni = 0; ni < 4; ni++) {
                int cb = wn * 32 + ni * 8;
                b[ni][0] = Bs[kc * 8 + tg    ][cb + g];
                b[ni][1] = Bs[kc * 8 + tg + 4][cb + g];
            }
            #pragma unroll
            for (int mi = 0; mi < 4; mi++)
                #pragma unroll
                for (int ni = 0; ni < 4; ni++)
                    mma8(acc[mi][ni], a[mi], b[ni]);
        }
        __syncthreads();
    }

    float* base = probs + (size_t)head * P * P;
    #pragma unroll
    for (int mi = 0; mi < 4; mi++) {
        int row = row0 + wm * 64 + mi * 16 + g;
        #pragma unroll
        for (int ni = 0; ni < 4; ni++) {
            int col = col0 + wn * 32 + ni * 8 + tg * 2;
            float2 lo = { acc[mi][ni][0] * 0.125f, acc[mi][ni][1] * 0.125f };
            float2 hi = { acc[mi][ni][2] * 0.125f, acc[mi][ni][3] * 0.125f };
            *(float2*)&base[(size_t)row * P + col]       = lo;
            *(float2*)&base[(size_t)(row + 8) * P + col] = hi;
        }
    }
}

// ============================================================================
// K3: in-place row softmax (unchanged).
// ============================================================================
__global__ __launch_bounds__(256) void softmax_kernel(float* __restrict__ probs)
{
    __shared__ float red[8];
    float* rowp = probs + (size_t)blockIdx.x * P;
    const int t = threadIdx.x;
    const int lane = t & 31;
    const int w = t >> 5;

    float4 v0 = ((float4*)rowp)[t];
    float4 v1 = ((float4*)rowp)[t + 256];

    float m = fmaxf(fmaxf(fmaxf(v0.x, v0.y), fmaxf(v0.z, v0.w)),
                    fmaxf(fmaxf(v1.x, v1.y), fmaxf(v1.z, v1.w)));
    #pragma unroll
    for (int o = 16; o; o >>= 1) m = fmaxf(m, __shfl_xor_sync(0xFFFFFFFFu, m, o));
    if (lane == 0) red[w] = m;
    __syncthreads();
    float bm = red[0];
    #pragma unroll
    for (int i = 1; i < 8; i++) bm = fmaxf(bm, red[i]);
    __syncthreads();

    v0.x = __expf(v0.x - bm); v0.y = __expf(v0.y - bm);
    v0.z = __expf(v0.z - bm); v0.w = __expf(v0.w - bm);
    v1.x = __expf(v1.x - bm); v1.y = __expf(v1.y - bm);
    v1.z = __expf(v1.z - bm); v1.w = __expf(v1.w - bm);
    float s = (v0.x + v0.y + v0.z + v0.w) + (v1.x + v1.y + v1.z + v1.w);
    #pragma unroll
    for (int o = 16; o; o >>= 1) s += __shfl_xor_sync(0xFFFFFFFFu, s, o);
    if (lane == 0) red[w] = s;
    __syncthreads();
    float bs = 0.f;
    #pragma unroll
    for (int i = 0; i < 8; i++) bs += red[i];

    float inv = 1.0f / bs;
    v0.x *= inv; v0.y *= inv; v0.z *= inv; v0.w *= inv;
    v1.x *= inv; v1.y *= inv; v1.z *= inv; v1.w *= inv;
    ((float4*)rowp)[t]       = v0;
    ((float4*)rowp)[t + 256] = v1;
}

// ============================================================================
// K4: PV via tf32 mma.sync.  attn[head][p][h] -> merged g_m[p][head*64+h]
// CTA: 128 rows x 64 cols, 8 warps, warp tile 32x32 (m-tiles 2, n-tiles 4).
// K = 2048, BK = 32 with register prefetch of next tile.
// As[r][k]  pad 36 ; Bs[s][h] pad 72 (stride%32==8 -> banks 8tg+g, clean).
// ============================================================================
__global__ __launch_bounds__(256) void pv_mma_kernel(const float* __restrict__ probs)
{
    __shared__ uint32_t As[128][36];
    __shared__ uint32_t Bs[32][72];

    const int t    = threadIdx.x;
    const int lane = t & 31;
    const int wid  = t >> 5;
    const int wm   = wid & 3;        // 0..3 (32-row group)
    const int wn   = wid >> 2;       // 0..1 (32-col group)
    const int g    = lane >> 2;
    const int tg   = lane & 3;
    const int head = blockIdx.z;
    const int row0 = blockIdx.x * 128;

    const float* A = probs + (size_t)head * P * P;

    // per-thread load coordinates
    const int ar[4] = { (t + 0)   >> 3, (t + 256) >> 3, (t + 512) >> 3, (t + 768) >> 3 };
    const int ac    = (t & 7) * 4;
    const int bk0   = (t + 0)   >> 4;
    const int bk1   = (t + 256) >> 4;
    const int bh    = (t & 15) * 4;

    float4 pa[4], pb[2];
    // prefetch k0 = 0
    #pragma unroll
    for (int it = 0; it < 4; it++)
        pa[it] = *(const float4*)&A[(size_t)(row0 + ar[it]) * P + ac];
    pb[0] = *(const float4*)&g_v[(size_t)bk0 * H + bh];
    pb[1] = *(const float4*)&g_v[(size_t)bk1 * H + bh];

    float acc[2][4][4] = {};

    for (int k0 = 0; k0 < P; k0 += 32) {
        // stage current tile
        #pragma unroll
        for (int it = 0; it < 4; it++) {
            uint4 u = { f2tf(pa[it].x), f2tf(pa[it].y), f2tf(pa[it].z), f2tf(pa[it].w) };
            *(uint4*)&As[ar[it]][ac] = u;
        }
        {
            uint4 u0 = { f2tf(pb[0].x), f2tf(pb[0].y), f2tf(pb[0].z), f2tf(pb[0].w) };
            uint4 u1 = { f2tf(pb[1].x), f2tf(pb[1].y), f2tf(pb[1].z), f2tf(pb[1].w) };
            *(uint4*)&Bs[bk0][bh] = u0;
            *(uint4*)&Bs[bk1][bh] = u1;
        }
        __syncthreads();

        // prefetch next tile into registers
        if (k0 + 32 < P) {
            #pragma unroll
            for (int it = 0; it < 4; it++)
                pa[it] = *(const float4*)&A[(size_t)(row0 + ar[it]) * P + k0 + 32 + ac];
            pb[0] = *(const float4*)&g_v[(size_t)(k0 + 32 + bk0) * H + bh];
            pb[1] = *(const float4*)&g_v[(size_t)(k0 + 32 + bk1) * H + bh];
        }

        #pragma unroll
        for (int kc = 0; kc < 4; kc++) {
            uint32_t a[2][4], b[4][2];
            #pragma unroll
            for (int mi = 0; mi < 2; mi++) {
                int rb = wm * 32 + mi * 16;
                a[mi][0] = As[rb + g    ][kc * 8 + tg    ];
                a[mi][1] = As[rb + g + 8][kc * 8 + tg    ];
                a[mi][2] = As[rb + g    ][kc * 8 + tg + 4];
                a[mi][3] = As[rb + g + 8][kc * 8 + tg + 4];
            }
            #pragma unroll
            for (int ni = 0; ni < 4; ni++) {
                int cb = wn * 32 + ni * 8;
                b[ni][0] = Bs[kc * 8 + tg    ][cb + g];
                b[ni][1] = Bs[kc * 8 + tg + 4][cb + g];
            }
            #pragma unroll
            for (int mi = 0; mi < 2; mi++)
                #pragma unroll
                for (int ni = 0; ni < 4; ni++)
                    mma8(acc[mi][ni], a[mi], b[ni]);
        }
        __syncthreads();
    }

    // epilogue: write merged layout
    #pragma unroll
    for (int mi = 0; mi < 2; mi++) {
        int row = row0 + wm * 32 + mi * 16 + g;
        #pragma unroll
        for (int ni = 0; ni < 4; ni++) {
            int col = wn * 32 + ni * 8 + tg * 2;
            float2 lo = { acc[mi][ni][0], acc[mi][ni][1] };
            float2 hi = { acc[mi][ni][2], acc[mi][ni][3] };
            *(float2*)&g_m[(size_t)row * (NQ * H) + head * H + col]       = lo;
            *(float2*)&g_m[(size_t)(row + 8) * (NQ * H) + head * H + col] = hi;
        }
    }
}

// ============================================================================
// K5: out projection (scalar fp32, unchanged).
// ============================================================================
__global__ __launch_bounds__(256) void outproj_kernel(
    const float* __restrict__ Wo, const float* __restrict__ bo,
    float* __restrict__ out)
{
    __shared__ float As[16][64];
    __shared__ float Bs[16][64];

    const int t  = threadIdx.x;
    const int tx = t & 15;
    const int ty = t >> 4;
    const int row0 = blockIdx.x * 64;

    const int lr = t >> 2;
    const int lk = (t & 3) * 4;

    float acc[4][4] = {};

    for (int k0 = 0; k0 < NQ * H; k0 += 16) {
        float4 av = *(const float4*)&g_m[(size_t)(row0 + lr) * (NQ * H) + k0 + lk];
        float4 bv = *(const float4*)&Wo[(size_t)lr * (NQ * H) + k0 + lk];
        As[lk + 0][lr] = av.x; As[lk + 1][lr] = av.y;
        As[lk + 2][lr] = av.z; As[lk + 3][lr] = av.w;
        Bs[lk + 0][lr] = bv.x; Bs[lk + 1][lr] = bv.y;
        Bs[lk + 2][lr] = bv.z; Bs[lk + 3][lr] = bv.w;
        __syncthreads();
        #pragma unroll
        for (int kk = 0; kk < 16; kk++) {
            float4 a = *(const float4*)&As[kk][ty * 4];
            float4 b = *(const float4*)&Bs[kk][tx * 4];
            float ar4[4] = {a.x, a.y, a.z, a.w};
            float br4[4] = {b.x, b.y, b.z, b.w};
            #pragma unroll
            for (int i = 0; i < 4; i++)
                #pragma unroll
                for (int j = 0; j < 4; j++)
                    acc[i][j] += ar4[i] * br4[j];
        }
        __syncthreads();
    }

    #pragma unroll
    for (int i = 0; i < 4; i++) {
        int row = row0 + ty * 4 + i;
        #pragma unroll
        for (int j = 0; j < 4; j++) {
            int h = tx * 4 + j;
            out[(size_t)row * H + h] = acc[i][j] + bo[h];
        }
    }
}

// ============================================================================
// launch
// ============================================================================
extern "C" void kernel_launch(void* const* d_in, const int* in_sizes, int n_in,
                              void* d_out, int out_size)
{
    const float* x  = (const float*)d_in[0];
    const float* Wq = (const float*)d_in[1];
    const float* bq = (const float*)d_in[2];
    const float* Wk = (const float*)d_in[3];
    const float* bk = (const float*)d_in[4];
    const float* Wv = (const float*)d_in[5];
    const float* bv = (const float*)d_in[6];
    const float* Wo = (const float*)d_in[7];
    const float* bo = (const float*)d_in[8];

    float* out   = (float*)d_out;            // [1, 2048, 64]
    float* probs = out + (size_t)P * H;      // [12, 2048, 2048]

    proj_kernel<<<dim3(P / 64, (E + 2 * H) / 64), 256>>>(x, Wq, bq, Wk, bk, Wv, bv);
    scores_mma_kernel<<<dim3(P / 128, P / 128, NQ), 256>>>(probs);
    softmax_kernel<<<NQ * P, 256>>>(probs);
    pv_mma_kernel<<<dim3(P / 128, 1, NQ), 256>>>(probs);
    outproj_kernel<<<P / 64, 256>>>(Wo, bo, out);
}